// round 10
// baseline (speedup 1.0000x reference)
#include <cuda_runtime.h>
#include <math.h>

#define SEQ_LEN 8192
#define HIDDEN  768
#define BATCH   8
#define NFFT    8192     // packed complex FFT size
#define MFFT    16384    // real FFT size
// padded layout: 16-element rows, stride 18 float2
#define PHYS18(i) ((((i) >> 4) * 18) + ((i) & 15))
#define SMEM_BYTES (512 * 18 * 8)   // 73728

// ---------------- static scratch (allocation-free rule) ----------------
__device__ float2 g_tw[NFFT];                         // exp(-2*pi*i*k/16384)
__device__ float2 g_twbr[4096];                       // tw[rev13(2*tt)]
__device__ float  g_k [SEQ_LEN * HIDDEN];             // filter (L, D)
__device__ float  g_kT[HIDDEN * SEQ_LEN];             // filter transposed (D, L)
__device__ float4 g_KfP[(size_t)HIDDEN * 4096];       // paired spectrum (F[f], F[8192-f])
__device__ float2 g_Kf4096[HIDDEN];                   // F[4096] per d
__device__ float  g_xT[(size_t)BATCH * HIDDEN * SEQ_LEN];
__device__ float  g_yT[(size_t)BATCH * HIDDEN * SEQ_LEN];

__device__ __forceinline__ float2 cmul(float2 a, float2 b) {
    return make_float2(a.x * b.x - a.y * b.y, a.x * b.y + a.y * b.x);
}
__device__ __forceinline__ float2 cmulc(float2 a, float2 b) {   // a * conj(b)
    return make_float2(a.x * b.x + a.y * b.y, a.y * b.x - a.x * b.y);
}
__device__ __forceinline__ float2 csq(float2 a) {
    return make_float2(a.x * a.x - a.y * a.y, 2.0f * a.x * a.y);
}
__device__ __forceinline__ float2 mulni(float2 a) {  // a * (-i)
    return make_float2(a.y, -a.x);
}

#define FBF(a, b, w) { float2 u_=(a), v_=(b); (a)=make_float2(u_.x+v_.x,u_.y+v_.y); \
                       float2 d_=make_float2(u_.x-v_.x,u_.y-v_.y); (b)=cmul(d_, (w)); }
#define FBF1(a, b)   { float2 u_=(a), v_=(b); (a)=make_float2(u_.x+v_.x,u_.y+v_.y); \
                       (b)=make_float2(u_.x-v_.x,u_.y-v_.y); }
#define FBFNI(a, b)  { float2 u_=(a), v_=(b); (a)=make_float2(u_.x+v_.x,u_.y+v_.y); \
                       (b)=make_float2(u_.y-v_.y, -(u_.x-v_.x)); }
#define IBF(a, b, w) { float2 u_=(a); float2 tv_=cmulc((b),(w)); \
                       (a)=make_float2(u_.x+tv_.x,u_.y+tv_.y); (b)=make_float2(u_.x-tv_.x,u_.y-tv_.y); }
#define IBF1(a, b)   FBF1(a, b)
#define IBFPI(a, b)  { float2 u_=(a), v_=(b); float2 tv_=make_float2(-v_.y, v_.x); \
                       (a)=make_float2(u_.x+tv_.x,u_.y+tv_.y); (b)=make_float2(u_.x-tv_.x,u_.y-tv_.y); }

#define C8f 0.70710678118654752f
#define CAf 0.92387953251128676f
#define CBf 0.38268343236508977f

// ---------------- twiddle init ----------------
__global__ void twiddle_init() {
    int k = blockIdx.x * blockDim.x + threadIdx.x;
    if (k < NFFT) {
        double a = -2.0 * M_PI * (double)k / (double)MFFT;
        g_tw[k] = make_float2((float)cos(a), (float)sin(a));
    }
    if (k < 4096) {
        int f = __brev(2 * k) >> 19;
        double a = -2.0 * M_PI * (double)f / (double)MFFT;
        g_twbr[k] = make_float2((float)cos(a), (float)sin(a));
    }
}

// ---------------- radix-8 butterfly helpers ----------------
__device__ __forceinline__ void bf8_fwd_tail(float2* x, float2 w1) {
    float2 w2 = csq(w1);
    float2 w4 = csq(w2);
    float2 w2n = mulni(w2);
    FBF(x[0], x[2], w2);  FBF(x[1], x[3], w2n);
    FBF(x[4], x[6], w2);  FBF(x[5], x[7], w2n);
    FBF(x[0], x[1], w4);  FBF(x[2], x[3], w4);
    FBF(x[4], x[5], w4);  FBF(x[6], x[7], w4);
}
__device__ __forceinline__ void bf8_fwd(float2* x, float2 w1) {
    float2 wr1 = cmul(w1, make_float2(C8f, -C8f));
    float2 wr2 = mulni(w1);
    float2 wr3 = cmul(w1, make_float2(-C8f, -C8f));
    FBF(x[0], x[4], w1);
    FBF(x[1], x[5], wr1);
    FBF(x[2], x[6], wr2);
    FBF(x[3], x[7], wr3);
    bf8_fwd_tail(x, w1);
}
__device__ __forceinline__ void bf8_inv(float2* x, float2 wB) {
    float2 wB2 = csq(wB);
    float2 wB4 = csq(wB2);
    IBF(x[0], x[1], wB4);  IBF(x[2], x[3], wB4);
    IBF(x[4], x[5], wB4);  IBF(x[6], x[7], wB4);
    float2 w2n = mulni(wB2);
    IBF(x[0], x[2], wB2);  IBF(x[1], x[3], w2n);
    IBF(x[4], x[6], wB2);  IBF(x[5], x[7], w2n);
    float2 wr1 = cmul(wB, make_float2(C8f, -C8f));
    float2 wr2 = mulni(wB);
    float2 wr3 = cmul(wB, make_float2(-C8f, -C8f));
    IBF(x[0], x[4], wB);
    IBF(x[1], x[5], wr1);
    IBF(x[2], x[6], wr2);
    IBF(x[3], x[7], wr3);
}
// last inverse pass: only lower outputs of final stage needed
__device__ __forceinline__ void bf8_inv_low(float2* x, float2 wB) {
    float2 wB2 = csq(wB);
    float2 wB4 = csq(wB2);
    IBF(x[0], x[1], wB4);  IBF(x[2], x[3], wB4);
    IBF(x[4], x[5], wB4);  IBF(x[6], x[7], wB4);
    float2 w2n = mulni(wB2);
    IBF(x[0], x[2], wB2);  IBF(x[1], x[3], w2n);
    IBF(x[4], x[6], wB2);  IBF(x[5], x[7], w2n);
    float2 wr1 = cmul(wB, make_float2(C8f, -C8f));
    float2 wr2 = mulni(wB);
    float2 wr3 = cmul(wB, make_float2(-C8f, -C8f));
    float2 t0 = cmulc(x[4], wB);
    float2 t1 = cmulc(x[5], wr1);
    float2 t2 = cmulc(x[6], wr2);
    float2 t3 = cmulc(x[7], wr3);
    x[0] = make_float2(x[0].x + t0.x, x[0].y + t0.y);
    x[1] = make_float2(x[1].x + t1.x, x[1].y + t1.y);
    x[2] = make_float2(x[2].x + t2.x, x[2].y + t2.y);
    x[3] = make_float2(x[3].x + t3.x, x[3].y + t3.y);
}

// ---------------- fused forward pass 1 (stages 0..2): global load + zero pad ----
__device__ __forceinline__ void fwd_pass1_fused(float2* S, int t, const float2* __restrict__ g) {
    float2 xA[8], xB[8];
#pragma unroll
    for (int e = 0; e < 4; e++) {
        float4 v = *reinterpret_cast<const float4*>(&g[2 * t + e * 1024]);
        xA[e] = make_float2(v.x, v.y);
        xB[e] = make_float2(v.z, v.w);
    }
    float2 w1A = g_tw[4 * t], w1B = g_tw[4 * t + 2];
    {
        float2 wr1 = cmul(w1A, make_float2(C8f, -C8f));
        float2 wr2 = mulni(w1A);
        float2 wr3 = cmul(w1A, make_float2(-C8f, -C8f));
        xA[4] = cmul(xA[0], w1A);
        xA[5] = cmul(xA[1], wr1);
        xA[6] = cmul(xA[2], wr2);
        xA[7] = cmul(xA[3], wr3);
    }
    bf8_fwd_tail(xA, w1A);
    {
        float2 wr1 = cmul(w1B, make_float2(C8f, -C8f));
        float2 wr2 = mulni(w1B);
        float2 wr3 = cmul(w1B, make_float2(-C8f, -C8f));
        xB[4] = cmul(xB[0], w1B);
        xB[5] = cmul(xB[1], wr1);
        xB[6] = cmul(xB[2], wr2);
        xB[7] = cmul(xB[3], wr3);
    }
    bf8_fwd_tail(xB, w1B);
#pragma unroll
    for (int e = 0; e < 8; e++)
        *reinterpret_cast<float4*>(&S[PHYS18(2 * t + e * 1024)]) =
            make_float4(xA[e].x, xA[e].y, xB[e].x, xB[e].y);
}

// ---------------- paired forward stages s..s+2 (s in {3,6}) ----------------
template<int s>
__device__ __forceinline__ void fwd_pair3(float2* S, int t) {
    const int h = 1 << (10 - s);
    const int u = t & (h / 2 - 1);
    const int r = 2 * u;
    const int base = ((t >> (9 - s)) << (13 - s)) | r;
    float2 xA[8], xB[8];
#pragma unroll
    for (int e = 0; e < 8; e++) {
        float4 v = *reinterpret_cast<const float4*>(&S[PHYS18(base + e * h)]);
        xA[e] = make_float2(v.x, v.y);
        xB[e] = make_float2(v.z, v.w);
    }
    bf8_fwd(xA, g_tw[r << (s + 1)]);
    bf8_fwd(xB, g_tw[(r + 1) << (s + 1)]);
#pragma unroll
    for (int e = 0; e < 8; e++)
        *reinterpret_cast<float4*>(&S[PHYS18(base + e * h)]) =
            make_float4(xA[e].x, xA[e].y, xB[e].x, xB[e].y);
}

// ---------------- forward stages 9..12 on 16 consecutive elements ----------------
__device__ __forceinline__ void fwd_group16(float2* S, int tid) {
    float4* row4 = reinterpret_cast<float4*>(S + tid * 18);
    float2 x[16];
#pragma unroll
    for (int e2 = 0; e2 < 8; e2++) {
        float4 v = row4[e2];
        x[2 * e2]     = make_float2(v.x, v.y);
        x[2 * e2 + 1] = make_float2(v.z, v.w);
    }
    FBF1 (x[0], x[8]);
    FBF  (x[1], x[9],  make_float2( CAf, -CBf));
    FBF  (x[2], x[10], make_float2( C8f, -C8f));
    FBF  (x[3], x[11], make_float2( CBf, -CAf));
    FBFNI(x[4], x[12]);
    FBF  (x[5], x[13], make_float2(-CBf, -CAf));
    FBF  (x[6], x[14], make_float2(-C8f, -C8f));
    FBF  (x[7], x[15], make_float2(-CAf, -CBf));
#pragma unroll
    for (int g = 0; g < 16; g += 8) {
        FBF1 (x[g+0], x[g+4]);
        FBF  (x[g+1], x[g+5], make_float2( C8f, -C8f));
        FBFNI(x[g+2], x[g+6]);
        FBF  (x[g+3], x[g+7], make_float2(-C8f, -C8f));
    }
#pragma unroll
    for (int g = 0; g < 16; g += 4) {
        FBF1 (x[g+0], x[g+2]);
        FBFNI(x[g+1], x[g+3]);
    }
#pragma unroll
    for (int g = 0; g < 16; g += 2) FBF1(x[g], x[g+1]);
#pragma unroll
    for (int e2 = 0; e2 < 8; e2++)
        row4[e2] = make_float4(x[2*e2].x, x[2*e2].y, x[2*e2+1].x, x[2*e2+1].y);
}

// ---------------- inverse stages 0..3 on 16 consecutive elements ----------------
__device__ __forceinline__ void inv_group16(float2* S, int tid) {
    float4* row4 = reinterpret_cast<float4*>(S + tid * 18);
    float2 x[16];
#pragma unroll
    for (int e2 = 0; e2 < 8; e2++) {
        float4 v = row4[e2];
        x[2 * e2]     = make_float2(v.x, v.y);
        x[2 * e2 + 1] = make_float2(v.z, v.w);
    }
#pragma unroll
    for (int g = 0; g < 16; g += 2) IBF1(x[g], x[g+1]);
#pragma unroll
    for (int g = 0; g < 16; g += 4) {
        IBF1 (x[g+0], x[g+2]);
        IBFPI(x[g+1], x[g+3]);
    }
#pragma unroll
    for (int g = 0; g < 16; g += 8) {
        IBF1 (x[g+0], x[g+4]);
        IBF  (x[g+1], x[g+5], make_float2( C8f, -C8f));
        IBFPI(x[g+2], x[g+6]);
        IBF  (x[g+3], x[g+7], make_float2(-C8f, -C8f));
    }
    IBF1 (x[0], x[8]);
    IBF  (x[1], x[9],  make_float2( CAf, -CBf));
    IBF  (x[2], x[10], make_float2( C8f, -C8f));
    IBF  (x[3], x[11], make_float2( CBf, -CAf));
    IBFPI(x[4], x[12]);
    IBF  (x[5], x[13], make_float2(-CBf, -CAf));
    IBF  (x[6], x[14], make_float2(-C8f, -C8f));
    IBF  (x[7], x[15], make_float2(-CAf, -CBf));
#pragma unroll
    for (int e2 = 0; e2 < 8; e2++)
        row4[e2] = make_float4(x[2*e2].x, x[2*e2].y, x[2*e2+1].x, x[2*e2+1].y);
}

// ---------------- paired inverse stages s0..s0+2 (s0 in {4,7}) -------
template<int s0>
__device__ __forceinline__ void inv_pair3(float2* S, int t) {
    const int h = 1 << s0;
    const int u = t & (h / 2 - 1);
    const int r = 2 * u;
    const int base = ((t >> (s0 - 1)) << (s0 + 3)) | r;
    float2 xA[8], xB[8];
#pragma unroll
    for (int e = 0; e < 8; e++) {
        float4 v = *reinterpret_cast<const float4*>(&S[PHYS18(base + e * h)]);
        xA[e] = make_float2(v.x, v.y);
        xB[e] = make_float2(v.z, v.w);
    }
    bf8_inv(xA, g_tw[r << (11 - s0)]);
    bf8_inv(xB, g_tw[(r + 1) << (11 - s0)]);
#pragma unroll
    for (int e = 0; e < 8; e++)
        *reinterpret_cast<float4*>(&S[PHYS18(base + e * h)]) =
            make_float4(xA[e].x, xA[e].y, xB[e].x, xB[e].y);
}

// ---------------- fused inverse final pass (stages 10..12) + scale + bias + store
__device__ __forceinline__ void inv_final_fused(float2* S, int t,
                                                float2* __restrict__ gdst,
                                                float scale, float bv) {
    float2 xA[8], xB[8];
#pragma unroll
    for (int e = 0; e < 8; e++) {
        float4 v = *reinterpret_cast<const float4*>(&S[PHYS18(2 * t + e * 1024)]);
        xA[e] = make_float2(v.x, v.y);
        xB[e] = make_float2(v.z, v.w);
    }
    bf8_inv_low(xA, g_tw[4 * t]);
    bf8_inv_low(xB, g_tw[4 * t + 2]);
#pragma unroll
    for (int e = 0; e < 4; e++)
        *reinterpret_cast<float4*>(&gdst[2 * t + e * 1024]) =
            make_float4(xA[e].x * scale + bv, xA[e].y * scale + bv,
                        xB[e].x * scale + bv, xB[e].y * scale + bv);
}

// ---------------- implicit filter MLP + modulation ----------------
__global__ void filter_kernel(
    const float* __restrict__ w_in,  const float* __restrict__ b_in,  const float* __restrict__ freq_in,
    const float* __restrict__ w_h0,  const float* __restrict__ b_h0,  const float* __restrict__ freq_h0,
    const float* __restrict__ w_h1,  const float* __restrict__ b_h1,  const float* __restrict__ freq_h1,
    const float* __restrict__ w_out)
{
    __shared__ float hA[16][64];
    __shared__ float hB[16][64];
    int l0 = blockIdx.x * 16;
    int tid = threadIdx.x;

    for (int idx = tid; idx < 16 * 64; idx += 256) {
        int ll = idx >> 6, j = idx & 63;
        int l = l0 + ll;
        float t0 = (float)l / (float)(SEQ_LEN - 1);
        float ang = (float)(2.0 * M_PI * 1e-4 / (double)SEQ_LEN) * (float)l;
        float z1 = cosf(ang), z2 = -sinf(ang);
        float v = t0 * w_in[j] + z1 * w_in[64 + j] + z2 * w_in[128 + j] + b_in[j];
        hA[ll][j] = sinf(freq_in[j] * v);
    }
    __syncthreads();
    for (int idx = tid; idx < 16 * 64; idx += 256) {
        int ll = idx >> 6, j = idx & 63;
        float acc = b_h0[j];
#pragma unroll
        for (int i = 0; i < 64; i++) acc += hA[ll][i] * w_h0[i * 64 + j];
        hB[ll][j] = sinf(freq_h0[j] * acc);
    }
    __syncthreads();
    for (int idx = tid; idx < 16 * 64; idx += 256) {
        int ll = idx >> 6, j = idx & 63;
        float acc = b_h1[j];
#pragma unroll
        for (int i = 0; i < 64; i++) acc += hB[ll][i] * w_h1[i * 64 + j];
        hA[ll][j] = sinf(freq_h1[j] * acc);
    }
    __syncthreads();

    const float MIND = 3.0701134573253943f;
    const float MAXD = 15.350567286626972f;
    for (int ll = 0; ll < 16; ll++) {
        int l = l0 + ll;
        float t0 = (float)l / (float)(SEQ_LEN - 1);
        for (int d = tid; d < HIDDEN; d += 256) {
            float acc = 0.f;
#pragma unroll
            for (int i = 0; i < 64; i++) acc += hA[ll][i] * w_out[i * HIDDEN + d];
            float ad = MIND + (MAXD - MIND) * ((float)d / 767.0f);
            g_k[(size_t)l * HIDDEN + d] = acc * expf(-t0 * ad);
        }
    }
}

// ---------------- transposes: 128(l) x 32(d) per block ----------------
__device__ __forceinline__ void transpose_LD_DL_body(const float* __restrict__ s,
                                                     float* __restrict__ dd,
                                                     int l0, int d0, int tx, int ty) {
    __shared__ float tile[4][32][33];
#pragma unroll
    for (int st = 0; st < 4; st++)
#pragma unroll
        for (int r = 0; r < 4; r++)
            tile[st][ty + r * 8][tx] =
                s[(size_t)(l0 + st * 32 + ty + r * 8) * HIDDEN + d0 + tx];
    __syncthreads();
#pragma unroll
    for (int st = 0; st < 4; st++)
#pragma unroll
        for (int r = 0; r < 4; r++)
            dd[(size_t)(d0 + ty + r * 8) * SEQ_LEN + l0 + st * 32 + tx] =
                tile[st][tx][ty + r * 8];
}

__global__ void transpose_in(const float* __restrict__ x) {
    int b = blockIdx.z;
    transpose_LD_DL_body(x + (size_t)b * SEQ_LEN * HIDDEN,
                         g_xT + (size_t)b * HIDDEN * SEQ_LEN,
                         blockIdx.x * 128, blockIdx.y * 32, threadIdx.x, threadIdx.y);
}

__global__ void transpose_k() {
    transpose_LD_DL_body(g_k, g_kT, blockIdx.x * 128, blockIdx.y * 32,
                         threadIdx.x, threadIdx.y);
}

__global__ void transpose_out(float* __restrict__ out) {
    __shared__ float tile[4][32][33];
    int b = blockIdx.z;
    int l0 = blockIdx.x * 128, d0 = blockIdx.y * 32;
    int tx = threadIdx.x, ty = threadIdx.y;
    const float* s = g_yT + (size_t)b * HIDDEN * SEQ_LEN;
    float* dd = out + (size_t)b * SEQ_LEN * HIDDEN;
#pragma unroll
    for (int st = 0; st < 4; st++)
#pragma unroll
        for (int r = 0; r < 4; r++)
            tile[st][ty + r * 8][tx] =
                s[(size_t)(d0 + ty + r * 8) * SEQ_LEN + l0 + st * 32 + tx];
    __syncthreads();
#pragma unroll
    for (int st = 0; st < 4; st++)
#pragma unroll
        for (int r = 0; r < 4; r++)
            dd[(size_t)(l0 + st * 32 + ty + r * 8) * HIDDEN + d0 + tx] =
                tile[st][tx][ty + r * 8];
}

// ---------------- kernel spectrum: writes position-paired KfP ----------------
__global__ void __launch_bounds__(512, 2) kf_kernel() {
    extern __shared__ float2 S[];
    int d = blockIdx.x;
    int tid = threadIdx.x;
    const float2* krow = (const float2*)(g_kT + (size_t)d * SEQ_LEN);
    fwd_pass1_fused(S, tid, krow);
    __syncthreads();
    fwd_pair3<3>(S, tid); __syncthreads();
    fwd_pair3<6>(S, tid); __syncthreads();
    fwd_group16(S, tid);  __syncthreads();

    const float invM = 1.0f / 16384.0f;
    float4* KfProw = g_KfP + (size_t)d * 4096;
    for (int tt = tid; tt < 4096; tt += 512) {
        if (tt == 0) {
            float2 c0 = S[PHYS18(0)];
            KfProw[0] = make_float4((c0.x + c0.y) * invM, 0.f,
                                    (c0.x - c0.y) * invM, 0.f);
            float2 C1 = S[PHYS18(1)];
            g_Kf4096[d] = make_float2(C1.x * invM, -C1.y * invM);
            continue;
        }
        int p  = 2 * tt;
        int f  = __brev(p) >> 19;
        int fc = 8192 - f;
        int q  = __brev(fc) >> 19;
        float2 C1 = S[PHYS18(p)], C2 = S[PHYS18(q)];
        float Ex = 0.5f * (C1.x + C2.x), Ey = 0.5f * (C1.y - C2.y);
        float Dx = C1.x - C2.x,          Dy = C1.y + C2.y;
        float Ox = 0.5f * Dy,            Oy = -0.5f * Dx;
        float2 w = g_twbr[tt];
        float wOx = Ox * w.x - Oy * w.y, wOy = Ox * w.y + Oy * w.x;
        KfProw[tt] = make_float4((Ex + wOx) * invM, (Ey + wOy) * invM,
                                 (Ex - wOx) * invM, -(Ey - wOy) * invM);
    }
}

// ---------------- fused conv ----------------
__global__ void __launch_bounds__(512, 2) conv_kernel(const float* __restrict__ bias) {
    extern __shared__ float2 S[];
    int col = blockIdx.x;           // b*768 + d
    int d   = col % HIDDEN;
    int tid = threadIdx.x;

    const float2* row = (const float2*)(g_xT + (size_t)col * SEQ_LEN);
    fwd_pass1_fused(S, tid, row);
    __syncthreads();
    fwd_pair3<3>(S, tid); __syncthreads();
    fwd_pair3<6>(S, tid); __syncthreads();
    fwd_group16(S, tid);  __syncthreads();

    const float4* KfProw = g_KfP + (size_t)d * 4096;
    for (int tt = tid; tt < 4096; tt += 512) {
        int p, q;
        float2 w, F1, F2;
        if (tt == 0) {
            // f = 0 / f = 8192 bin at position 0
            float2 c0 = S[PHYS18(0)];
            float4 kp0 = KfProw[0];
            float U0 = c0.x + c0.y, UN = c0.x - c0.y;
            float2 Y0 = make_float2(U0 * kp0.x, U0 * kp0.y);
            float2 YN = make_float2(UN * kp0.z, UN * kp0.w);
            float Eyx = 0.5f * (Y0.x + YN.x), Eyy = 0.5f * (Y0.y + YN.y);
            float Dyx = 0.5f * (Y0.x - YN.x), Dyy = 0.5f * (Y0.y - YN.y);
            S[PHYS18(0)] = make_float2(Eyx - Dyy, Eyy + Dyx);
            // f = 4096 self-pair at position 1
            p = 1; q = 1;
            w = make_float2(0.f, -1.f);
            F1 = g_Kf4096[d];
            F2 = F1;
        } else {
            p = 2 * tt;
            int f  = __brev(p) >> 19;
            int fc = 8192 - f;
            q = __brev(fc) >> 19;
            w = g_twbr[tt];
            float4 kp = KfProw[tt];
            F1 = make_float2(kp.x, kp.y);
            F2 = make_float2(kp.z, kp.w);
        }
        int qp = PHYS18(p), qq = PHYS18(q);
        float2 C1 = S[qp], C2 = S[qq];
        float Ex = 0.5f * (C1.x + C2.x), Ey = 0.5f * (C1.y - C2.y);
        float Dx = C1.x - C2.x,          Dy = C1.y + C2.y;
        float Ox = 0.5f * Dy,            Oy = -0.5f * Dx;
        float wOx = Ox * w.x - Oy * w.y, wOy = Ox * w.y + Oy * w.x;
        float2 Uk  = make_float2(Ex + wOx, Ey + wOy);
        float2 UkN = make_float2(Ex - wOx, Ey - wOy);
        float2 Y1 = cmul(Uk, F1);
        float2 Y2 = cmul(UkN, make_float2(F2.x, -F2.y));
        float2 Eyc = make_float2(0.5f * (Y1.x + Y2.x), 0.5f * (Y1.y + Y2.y));
        float2 Dyc = make_float2(0.5f * (Y1.x - Y2.x), 0.5f * (Y1.y - Y2.y));
        float2 Oyc = make_float2(Dyc.x * w.x + Dyc.y * w.y, Dyc.y * w.x - Dyc.x * w.y);
        float2 Zk  = make_float2(Eyc.x - Oyc.y, Eyc.y + Oyc.x);
        float2 Y1p = cmul(make_float2(UkN.x, -UkN.y), F2);
        float2 Y2p = cmul(make_float2(Uk.x, -Uk.y), make_float2(F1.x, -F1.y));
        float2 w2  = make_float2(-w.x, w.y);
        float2 Eyp = make_float2(0.5f * (Y1p.x + Y2p.x), 0.5f * (Y1p.y + Y2p.y));
        float2 Dyp = make_float2(0.5f * (Y1p.x - Y2p.x), 0.5f * (Y1p.y - Y2p.y));
        float2 Oyp = make_float2(Dyp.x * w2.x + Dyp.y * w2.y, Dyp.y * w2.x - Dyp.x * w2.y);
        float2 Zk2 = make_float2(Eyp.x - Oyp.y, Eyp.y + Oyp.x);
        S[qp] = Zk;
        S[qq] = Zk2;
    }
    __syncthreads();

    inv_group16(S, tid);  __syncthreads();
    inv_pair3<4>(S, tid); __syncthreads();
    inv_pair3<7>(S, tid); __syncthreads();

    const float invN = 1.0f / 8192.0f;
    float bv = bias[d];
    float2* orow = (float2*)(g_yT + (size_t)col * SEQ_LEN);
    inv_final_fused(S, tid, orow, invN, bv);
}

// ---------------- launch ----------------
extern "C" void kernel_launch(void* const* d_in, const int* in_sizes, int n_in,
                              void* d_out, int out_size) {
    const float* x       = (const float*)d_in[0];
    const float* w_in    = (const float*)d_in[1];
    const float* b_in    = (const float*)d_in[2];
    const float* freq_in = (const float*)d_in[3];
    const float* w_h0    = (const float*)d_in[4];
    const float* b_h0    = (const float*)d_in[5];
    const float* freq_h0 = (const float*)d_in[6];
    const float* w_h1    = (const float*)d_in[7];
    const float* b_h1    = (const float*)d_in[8];
    const float* freq_h1 = (const float*)d_in[9];
    const float* w_out   = (const float*)d_in[10];
    const float* bias    = (const float*)d_in[11];
    float* out = (float*)d_out;

    cudaFuncSetAttribute(kf_kernel,   cudaFuncAttributeMaxDynamicSharedMemorySize, SMEM_BYTES);
    cudaFuncSetAttribute(conv_kernel, cudaFuncAttributeMaxDynamicSharedMemorySize, SMEM_BYTES);

    twiddle_init<<<16, 512>>>();
    filter_kernel<<<SEQ_LEN / 16, 256>>>(w_in, b_in, freq_in, w_h0, b_h0, freq_h0,
                                         w_h1, b_h1, freq_h1, w_out);
    dim3 tblk(32, 8);
    dim3 tgrid(SEQ_LEN / 128, HIDDEN / 32, BATCH);
    transpose_in<<<tgrid, tblk>>>(x);
    dim3 kgrid(SEQ_LEN / 128, HIDDEN / 32, 1);
    transpose_k<<<kgrid, tblk>>>();
    kf_kernel<<<HIDDEN, 512, SMEM_BYTES>>>();
    conv_kernel<<<BATCH * HIDDEN, 512, SMEM_BYTES>>>(bias);
    transpose_out<<<tgrid, tblk>>>(out);
}

// round 11
// speedup vs baseline: 1.0399x; 1.0399x over previous
#include <cuda_runtime.h>
#include <math.h>

#define SEQ_LEN 8192
#define HIDDEN  768
#define BATCH   8
#define NFFT    8192     // packed complex FFT size
#define MFFT    16384    // real FFT size
#define SMEM_BYTES (NFFT * 8)   // 65536

// ---------------- static scratch (allocation-free rule) ----------------
__device__ float2 g_tw[NFFT];                         // exp(-2*pi*i*k/16384)
__device__ float  g_kT[HIDDEN * SEQ_LEN];             // filter transposed (D, L)
__device__ float2 g_Kf[HIDDEN * (NFFT + 1)];          // rfft(k)/16384 per d
__device__ float  g_xT[(size_t)BATCH * HIDDEN * SEQ_LEN];  // x transposed (B*D, L)
__device__ float  g_yT[(size_t)BATCH * HIDDEN * SEQ_LEN];  // y transposed (B*D, L)

__device__ __forceinline__ float2 cmul(float2 a, float2 b) {
    return make_float2(a.x * b.x - a.y * b.y, a.x * b.y + a.y * b.x);
}
__device__ __forceinline__ float2 cmulc(float2 a, float2 b) {   // a * conj(b)
    return make_float2(a.x * b.x + a.y * b.y, a.y * b.x - a.x * b.y);
}
__device__ __forceinline__ float2 csq(float2 a) {
    return make_float2(a.x * a.x - a.y * a.y, 2.0f * a.x * a.y);
}
__device__ __forceinline__ float2 mulni(float2 a) {  // a * (-i)
    return make_float2(a.y, -a.x);
}
// XOR-swizzled physical index: conflict-free for strided FFT passes and
// 2-way worst case for the bit-reversed pointwise pass.
__device__ __forceinline__ int PHYS(int i) {
    return (i & ~15) | ((i ^ (i >> 4) ^ (i >> 8)) & 15);
}

#define FBF(a, b, w) { float2 u_=(a), v_=(b); (a)=make_float2(u_.x+v_.x,u_.y+v_.y); \
                       float2 d_=make_float2(u_.x-v_.x,u_.y-v_.y); (b)=cmul(d_, (w)); }
#define FBF1(a, b)   { float2 u_=(a), v_=(b); (a)=make_float2(u_.x+v_.x,u_.y+v_.y); \
                       (b)=make_float2(u_.x-v_.x,u_.y-v_.y); }
#define FBFNI(a, b)  { float2 u_=(a), v_=(b); (a)=make_float2(u_.x+v_.x,u_.y+v_.y); \
                       (b)=make_float2(u_.y-v_.y, -(u_.x-v_.x)); }
#define IBF(a, b, w) { float2 u_=(a); float2 tv_=cmulc((b),(w)); \
                       (a)=make_float2(u_.x+tv_.x,u_.y+tv_.y); (b)=make_float2(u_.x-tv_.x,u_.y-tv_.y); }
#define IBF1(a, b)   FBF1(a, b)
#define IBFPI(a, b)  { float2 u_=(a), v_=(b); float2 tv_=make_float2(-v_.y, v_.x); \
                       (a)=make_float2(u_.x+tv_.x,u_.y+tv_.y); (b)=make_float2(u_.x-tv_.x,u_.y-tv_.y); }

#define C8f 0.70710678118654752f
#define CAf 0.92387953251128676f
#define CBf 0.38268343236508977f

// ---------------- twiddle init ----------------
__global__ void twiddle_init() {
    int k = blockIdx.x * blockDim.x + threadIdx.x;
    if (k < NFFT) {
        double a = -2.0 * M_PI * (double)k / (double)MFFT;
        g_tw[k] = make_float2((float)cos(a), (float)sin(a));
    }
}

// ---------------- fused forward pass 1 (stages 0,1,2): global load + zero pad ----
__device__ __forceinline__ void fwd_pass1_fused(float2* S, int tid, const float2* __restrict__ g) {
#pragma unroll
    for (int it = 0; it < 2; it++) {
        int t = tid + it * 512;           // base = t, r = t
        float2 x[8];
#pragma unroll
        for (int e = 0; e < 4; e++) x[e] = g[t + e * 1024];
        float2 w1 = g_tw[t << 1];
        float2 w2 = csq(w1);
        float2 w4 = csq(w2);
        // stage 0 with zero upper half
        {
            float2 wr1 = cmul(w1, make_float2(C8f, -C8f));
            float2 wr2 = mulni(w1);
            float2 wr3 = cmul(w1, make_float2(-C8f, -C8f));
            x[4] = cmul(x[0], w1);
            x[5] = cmul(x[1], wr1);
            x[6] = cmul(x[2], wr2);
            x[7] = cmul(x[3], wr3);
        }
        // stage 1
        {
            float2 w2n = mulni(w2);
            FBF(x[0], x[2], w2);
            FBF(x[1], x[3], w2n);
            FBF(x[4], x[6], w2);
            FBF(x[5], x[7], w2n);
        }
        // stage 2
        FBF(x[0], x[1], w4);
        FBF(x[2], x[3], w4);
        FBF(x[4], x[5], w4);
        FBF(x[6], x[7], w4);
#pragma unroll
        for (int e = 0; e < 8; e++) S[PHYS(t + e * 1024)] = x[e];
    }
}

// ---------------- grouped forward stages s, s+1, s+2 (s in {3,6}) ----------------
template<int s>
__device__ __forceinline__ void fwd_group3(float2* S, int tid) {
    const int h = 1 << (10 - s);
#pragma unroll
    for (int it = 0; it < 2; it++) {
        int t = tid + it * 512;
        int r = t & (h - 1);
        int base = ((t >> (10 - s)) << (13 - s)) | r;
        float2 x[8];
#pragma unroll
        for (int e = 0; e < 8; e++) x[e] = S[PHYS(base + e * h)];
        float2 w1 = g_tw[r << (s + 1)];
        float2 w2 = csq(w1);
        float2 w4 = csq(w2);
        {
            float2 wr1 = cmul(w1, make_float2(C8f, -C8f));
            float2 wr2 = mulni(w1);
            float2 wr3 = cmul(w1, make_float2(-C8f, -C8f));
            FBF(x[0], x[4], w1);
            FBF(x[1], x[5], wr1);
            FBF(x[2], x[6], wr2);
            FBF(x[3], x[7], wr3);
        }
        {
            float2 w2n = mulni(w2);
            FBF(x[0], x[2], w2);
            FBF(x[1], x[3], w2n);
            FBF(x[4], x[6], w2);
            FBF(x[5], x[7], w2n);
        }
        FBF(x[0], x[1], w4);
        FBF(x[2], x[3], w4);
        FBF(x[4], x[5], w4);
        FBF(x[6], x[7], w4);
#pragma unroll
        for (int e = 0; e < 8; e++) S[PHYS(base + e * h)] = x[e];
    }
}

// ---------------- forward stages 9..12 on 16 consecutive elements ----------------
__device__ __forceinline__ void fwd_group16(float2* S, int tid) {
    float2* row = S + tid * 16;
    int hh = (tid ^ (tid >> 4)) & 15;        // PHYS(16*tid + e) = 16*tid + (e ^ hh)
    float2 x[16];
#pragma unroll
    for (int e = 0; e < 16; e++) x[e] = row[e ^ hh];
    FBF1 (x[0], x[8]);
    FBF  (x[1], x[9],  make_float2( CAf, -CBf));
    FBF  (x[2], x[10], make_float2( C8f, -C8f));
    FBF  (x[3], x[11], make_float2( CBf, -CAf));
    FBFNI(x[4], x[12]);
    FBF  (x[5], x[13], make_float2(-CBf, -CAf));
    FBF  (x[6], x[14], make_float2(-C8f, -C8f));
    FBF  (x[7], x[15], make_float2(-CAf, -CBf));
#pragma unroll
    for (int g = 0; g < 16; g += 8) {
        FBF1 (x[g+0], x[g+4]);
        FBF  (x[g+1], x[g+5], make_float2( C8f, -C8f));
        FBFNI(x[g+2], x[g+6]);
        FBF  (x[g+3], x[g+7], make_float2(-C8f, -C8f));
    }
#pragma unroll
    for (int g = 0; g < 16; g += 4) {
        FBF1 (x[g+0], x[g+2]);
        FBFNI(x[g+1], x[g+3]);
    }
#pragma unroll
    for (int g = 0; g < 16; g += 2) FBF1(x[g], x[g+1]);
#pragma unroll
    for (int e = 0; e < 16; e++) row[e ^ hh] = x[e];
}

// ---------------- inverse stages 0..3 on 16 consecutive elements ----------------
__device__ __forceinline__ void inv_group16(float2* S, int tid) {
    float2* row = S + tid * 16;
    int hh = (tid ^ (tid >> 4)) & 15;
    float2 x[16];
#pragma unroll
    for (int e = 0; e < 16; e++) x[e] = row[e ^ hh];
#pragma unroll
    for (int g = 0; g < 16; g += 2) IBF1(x[g], x[g+1]);
#pragma unroll
    for (int g = 0; g < 16; g += 4) {
        IBF1 (x[g+0], x[g+2]);
        IBFPI(x[g+1], x[g+3]);
    }
#pragma unroll
    for (int g = 0; g < 16; g += 8) {
        IBF1 (x[g+0], x[g+4]);
        IBF  (x[g+1], x[g+5], make_float2( C8f, -C8f));
        IBFPI(x[g+2], x[g+6]);
        IBF  (x[g+3], x[g+7], make_float2(-C8f, -C8f));
    }
    IBF1 (x[0], x[8]);
    IBF  (x[1], x[9],  make_float2( CAf, -CBf));
    IBF  (x[2], x[10], make_float2( C8f, -C8f));
    IBF  (x[3], x[11], make_float2( CBf, -CAf));
    IBFPI(x[4], x[12]);
    IBF  (x[5], x[13], make_float2(-CBf, -CAf));
    IBF  (x[6], x[14], make_float2(-C8f, -C8f));
    IBF  (x[7], x[15], make_float2(-CAf, -CBf));
#pragma unroll
    for (int e = 0; e < 16; e++) row[e ^ hh] = x[e];
}

// ---------------- grouped inverse stages s0, s0+1, s0+2 (s0 in {4,7}) -------
template<int s0>
__device__ __forceinline__ void inv_group3(float2* S, int tid) {
    const int h = 1 << s0;
#pragma unroll
    for (int it = 0; it < 2; it++) {
        int t = tid + it * 512;
        int r = t & (h - 1);
        int base = ((t >> s0) << (s0 + 3)) | r;
        float2 x[8];
#pragma unroll
        for (int e = 0; e < 8; e++) x[e] = S[PHYS(base + e * h)];
        float2 wB = g_tw[r << (11 - s0)];
        float2 wB2 = csq(wB);
        float2 wB4 = csq(wB2);
        IBF(x[0], x[1], wB4);
        IBF(x[2], x[3], wB4);
        IBF(x[4], x[5], wB4);
        IBF(x[6], x[7], wB4);
        {
            float2 w2n = mulni(wB2);
            IBF(x[0], x[2], wB2);
            IBF(x[1], x[3], w2n);
            IBF(x[4], x[6], wB2);
            IBF(x[5], x[7], w2n);
        }
        {
            float2 wr1 = cmul(wB, make_float2(C8f, -C8f));
            float2 wr2 = mulni(wB);
            float2 wr3 = cmul(wB, make_float2(-C8f, -C8f));
            IBF(x[0], x[4], wB);
            IBF(x[1], x[5], wr1);
            IBF(x[2], x[6], wr2);
            IBF(x[3], x[7], wr3);
        }
#pragma unroll
        for (int e = 0; e < 8; e++) S[PHYS(base + e * h)] = x[e];
    }
}

// ---------------- fused inverse final pass (stages 10,11,12) --------------------
__device__ __forceinline__ void inv_pass4_fused(float2* S, int tid,
                                                float2* __restrict__ gdst,
                                                float scale, float bv) {
#pragma unroll
    for (int it = 0; it < 2; it++) {
        int t = tid + it * 512;           // base = t, r = t (s0 = 10)
        float2 x[8];
#pragma unroll
        for (int e = 0; e < 8; e++) x[e] = S[PHYS(t + e * 1024)];
        float2 wB = g_tw[t << 1];
        float2 wB2 = csq(wB);
        float2 wB4 = csq(wB2);
        IBF(x[0], x[1], wB4);
        IBF(x[2], x[3], wB4);
        IBF(x[4], x[5], wB4);
        IBF(x[6], x[7], wB4);
        {
            float2 w2n = mulni(wB2);
            IBF(x[0], x[2], wB2);
            IBF(x[1], x[3], w2n);
            IBF(x[4], x[6], wB2);
            IBF(x[5], x[7], w2n);
        }
        {
            float2 wr1 = cmul(wB, make_float2(C8f, -C8f));
            float2 wr2 = mulni(wB);
            float2 wr3 = cmul(wB, make_float2(-C8f, -C8f));
            float2 t0 = cmulc(x[4], wB);
            float2 t1 = cmulc(x[5], wr1);
            float2 t2 = cmulc(x[6], wr2);
            float2 t3 = cmulc(x[7], wr3);
            x[0] = make_float2(x[0].x + t0.x, x[0].y + t0.y);
            x[1] = make_float2(x[1].x + t1.x, x[1].y + t1.y);
            x[2] = make_float2(x[2].x + t2.x, x[2].y + t2.y);
            x[3] = make_float2(x[3].x + t3.x, x[3].y + t3.y);
        }
#pragma unroll
        for (int e = 0; e < 4; e++)
            gdst[t + e * 1024] = make_float2(x[e].x * scale + bv, x[e].y * scale + bv);
    }
}

// ---------------- implicit filter MLP + modulation, writes g_kT directly --------
// Dynamic smem: hA[16][64], hB[16][64], ktile[768][17]
__global__ void filter_kernel(
    const float* __restrict__ w_in,  const float* __restrict__ b_in,  const float* __restrict__ freq_in,
    const float* __restrict__ w_h0,  const float* __restrict__ b_h0,  const float* __restrict__ freq_h0,
    const float* __restrict__ w_h1,  const float* __restrict__ b_h1,  const float* __restrict__ freq_h1,
    const float* __restrict__ w_out)
{
    extern __shared__ float sm[];
    float* hA    = sm;              // 16*64
    float* hB    = sm + 1024;       // 16*64
    float* ktile = sm + 2048;       // 768*17
    int l0 = blockIdx.x * 16;
    int tid = threadIdx.x;

    for (int idx = tid; idx < 16 * 64; idx += 256) {
        int ll = idx >> 6, j = idx & 63;
        int l = l0 + ll;
        float t0 = (float)l / (float)(SEQ_LEN - 1);
        float ang = (float)(2.0 * M_PI * 1e-4 / (double)SEQ_LEN) * (float)l;
        float z1 = cosf(ang), z2 = -sinf(ang);
        float v = t0 * w_in[j] + z1 * w_in[64 + j] + z2 * w_in[128 + j] + b_in[j];
        hA[ll * 64 + j] = sinf(freq_in[j] * v);
    }
    __syncthreads();
    for (int idx = tid; idx < 16 * 64; idx += 256) {
        int ll = idx >> 6, j = idx & 63;
        float acc = b_h0[j];
#pragma unroll
        for (int i = 0; i < 64; i++) acc += hA[ll * 64 + i] * w_h0[i * 64 + j];
        hB[ll * 64 + j] = sinf(freq_h0[j] * acc);
    }
    __syncthreads();
    for (int idx = tid; idx < 16 * 64; idx += 256) {
        int ll = idx >> 6, j = idx & 63;
        float acc = b_h1[j];
#pragma unroll
        for (int i = 0; i < 64; i++) acc += hB[ll * 64 + i] * w_h1[i * 64 + j];
        hA[ll * 64 + j] = sinf(freq_h1[j] * acc);
    }
    __syncthreads();

    const float MIND = 3.0701134573253943f;
    const float MAXD = 15.350567286626972f;
    for (int ll = 0; ll < 16; ll++) {
        int l = l0 + ll;
        float t0 = (float)l / (float)(SEQ_LEN - 1);
        for (int d = tid; d < HIDDEN; d += 256) {
            float acc = 0.f;
#pragma unroll
            for (int i = 0; i < 64; i++) acc += hA[ll * 64 + i] * w_out[i * HIDDEN + d];
            float ad = MIND + (MAXD - MIND) * ((float)d / 767.0f);
            ktile[d * 17 + ll] = acc * expf(-t0 * ad);
        }
    }
    __syncthreads();

    // write 768 rows of 16 floats each (64 B contiguous per row) as 4x float4
#pragma unroll
    for (int j = 0; j < 3; j++) {
        int row = j * 256 + tid;
        const float* kr = ktile + row * 17;
        float* dst = g_kT + (size_t)row * SEQ_LEN + l0;
        *reinterpret_cast<float4*>(dst)      = make_float4(kr[0],  kr[1],  kr[2],  kr[3]);
        *reinterpret_cast<float4*>(dst + 4)  = make_float4(kr[4],  kr[5],  kr[6],  kr[7]);
        *reinterpret_cast<float4*>(dst + 8)  = make_float4(kr[8],  kr[9],  kr[10], kr[11]);
        *reinterpret_cast<float4*>(dst + 12) = make_float4(kr[12], kr[13], kr[14], kr[15]);
    }
}

// ---------------- transposes: 128(l) x 32(d) per block, float2 on L side --------
__global__ void transpose_in(const float* __restrict__ x) {
    __shared__ float tile[128][33];
    int b = blockIdx.z;
    int l0 = blockIdx.x * 128, d0 = blockIdx.y * 32;
    int tx = threadIdx.x, ty = threadIdx.y;   // (32, 8)
    const float* xb = x + (size_t)b * SEQ_LEN * HIDDEN;
#pragma unroll
    for (int j = 0; j < 16; j++) {
        int ll = j * 8 + ty;
        tile[ll][tx] = xb[(size_t)(l0 + ll) * HIDDEN + d0 + tx];
    }
    __syncthreads();
    float* dst = g_xT + (size_t)(b * HIDDEN + d0) * SEQ_LEN;
    int tid = ty * 32 + tx;
#pragma unroll
    for (int j = 0; j < 8; j++) {
        int idx = j * 256 + tid;   // 0..2047
        int dr = idx >> 6;         // 0..31
        int l2 = idx & 63;         // 0..63
        float2 v = make_float2(tile[2 * l2][dr], tile[2 * l2 + 1][dr]);
        *reinterpret_cast<float2*>(&dst[(size_t)dr * SEQ_LEN + l0 + 2 * l2]) = v;
    }
}

__global__ void transpose_out(float* __restrict__ out) {
    __shared__ float tile[128][33];
    int b = blockIdx.z;
    int l0 = blockIdx.x * 128, d0 = blockIdx.y * 32;
    int tx = threadIdx.x, ty = threadIdx.y;
    const float* src = g_yT + (size_t)(b * HIDDEN + d0) * SEQ_LEN;
    int tid = ty * 32 + tx;
#pragma unroll
    for (int j = 0; j < 8; j++) {
        int idx = j * 256 + tid;
        int dr = idx >> 6;
        int l2 = idx & 63;
        float2 v = *reinterpret_cast<const float2*>(&src[(size_t)dr * SEQ_LEN + l0 + 2 * l2]);
        tile[2 * l2][dr]     = v.x;
        tile[2 * l2 + 1][dr] = v.y;
    }
    __syncthreads();
    float* ob = out + (size_t)b * SEQ_LEN * HIDDEN;
#pragma unroll
    for (int j = 0; j < 16; j++) {
        int ll = j * 8 + ty;
        ob[(size_t)(l0 + ll) * HIDDEN + d0 + tx] = tile[ll][tx];
    }
}

// ---------------- kernel spectrum ----------------
__global__ void __launch_bounds__(512, 3) kf_kernel() {
    extern __shared__ float2 S[];
    int d = blockIdx.x;
    int tid = threadIdx.x;
    const float2* krow = (const float2*)(g_kT + (size_t)d * SEQ_LEN);
    fwd_pass1_fused(S, tid, krow);
    __syncthreads();
    fwd_group3<3>(S, tid); __syncthreads();
    fwd_group3<6>(S, tid); __syncthreads();
    fwd_group16(S, tid);   __syncthreads();

    const float invM = 1.0f / 16384.0f;
    float2* Kf = g_Kf + (size_t)d * (NFFT + 1);
    if (tid == 0) {
        float2 c0 = S[PHYS(0)];
        Kf[0]    = make_float2((c0.x + c0.y) * invM, 0.f);
        Kf[NFFT] = make_float2((c0.x - c0.y) * invM, 0.f);
    }
    for (int t = tid; t < 4096; t += 512) {
        int k  = t + 1;
        int p1 = __brev(k) >> 19;
        int p2 = __brev(8192 - k) >> 19;
        float2 C1 = S[PHYS(p1)], C2 = S[PHYS(p2)];
        float Ex = 0.5f * (C1.x + C2.x), Ey = 0.5f * (C1.y - C2.y);
        float Dx = C1.x - C2.x,          Dy = C1.y + C2.y;
        float Ox = 0.5f * Dy,            Oy = -0.5f * Dx;
        float2 w = g_tw[k];
        float wOx = Ox * w.x - Oy * w.y, wOy = Ox * w.y + Oy * w.x;
        Kf[k]        = make_float2((Ex + wOx) * invM, (Ey + wOy) * invM);
        Kf[8192 - k] = make_float2((Ex - wOx) * invM, -(Ey - wOy) * invM);
    }
}

// ---------------- fused conv ----------------
__global__ void __launch_bounds__(512, 3) conv_kernel(const float* __restrict__ bias) {
    extern __shared__ float2 S[];
    int col = blockIdx.x;           // b*768 + d
    int d   = col % HIDDEN;
    int tid = threadIdx.x;

    const float2* row = (const float2*)(g_xT + (size_t)col * SEQ_LEN);
    fwd_pass1_fused(S, tid, row);
    __syncthreads();
    fwd_group3<3>(S, tid); __syncthreads();
    fwd_group3<6>(S, tid); __syncthreads();
    fwd_group16(S, tid);   __syncthreads();

    const float2* Kf = g_Kf + (size_t)d * (NFFT + 1);
    if (tid == 0) {
        float2 c0 = S[PHYS(0)];
        float U0 = c0.x + c0.y, UN = c0.x - c0.y;
        float2 F0 = Kf[0], FN = Kf[NFFT];
        float2 Y0 = make_float2(U0 * F0.x, U0 * F0.y);
        float2 YN = make_float2(UN * FN.x, UN * FN.y);
        float Eyx = 0.5f * (Y0.x + YN.x), Eyy = 0.5f * (Y0.y + YN.y);
        float Dyx = 0.5f * (Y0.x - YN.x), Dyy = 0.5f * (Y0.y - YN.y);
        S[PHYS(0)] = make_float2(Eyx - Dyy, Eyy + Dyx);
    }
    for (int t = tid; t < 4096; t += 512) {
        int k  = t + 1;
        int k2 = 8192 - k;
        int p1 = __brev(k)  >> 19;
        int p2 = __brev(k2) >> 19;
        int q1 = PHYS(p1), q2 = PHYS(p2);
        float2 C1 = S[q1], C2 = S[q2];
        float Ex = 0.5f * (C1.x + C2.x), Ey = 0.5f * (C1.y - C2.y);
        float Dx = C1.x - C2.x,          Dy = C1.y + C2.y;
        float Ox = 0.5f * Dy,            Oy = -0.5f * Dx;
        float2 w = g_tw[k];
        float wOx = Ox * w.x - Oy * w.y, wOy = Ox * w.y + Oy * w.x;
        float2 Uk  = make_float2(Ex + wOx, Ey + wOy);
        float2 UkN = make_float2(Ex - wOx, Ey - wOy);
        float2 F1 = Kf[k];
        float2 F2 = Kf[k2];
        float2 Y1 = cmul(Uk, F1);
        float2 Y2 = cmul(UkN, make_float2(F2.x, -F2.y));
        float2 Eyc = make_float2(0.5f * (Y1.x + Y2.x), 0.5f * (Y1.y + Y2.y));
        float2 Dyc = make_float2(0.5f * (Y1.x - Y2.x), 0.5f * (Y1.y - Y2.y));
        float2 Oyc = make_float2(Dyc.x * w.x + Dyc.y * w.y, Dyc.y * w.x - Dyc.x * w.y);
        float2 Zk  = make_float2(Eyc.x - Oyc.y, Eyc.y + Oyc.x);
        // mirror bin: w2 = g_tw[8192-k] = (-w.x, w.y)
        float2 Y1p = cmul(make_float2(UkN.x, -UkN.y), F2);
        float2 Y2p = cmul(make_float2(Uk.x, -Uk.y), make_float2(F1.x, -F1.y));
        float2 w2  = make_float2(-w.x, w.y);
        float2 Eyp = make_float2(0.5f * (Y1p.x + Y2p.x), 0.5f * (Y1p.y + Y2p.y));
        float2 Dyp = make_float2(0.5f * (Y1p.x - Y2p.x), 0.5f * (Y1p.y - Y2p.y));
        float2 Oyp = make_float2(Dyp.x * w2.x + Dyp.y * w2.y, Dyp.y * w2.x - Dyp.x * w2.y);
        float2 Zk2 = make_float2(Eyp.x - Oyp.y, Eyp.y + Oyp.x);
        S[q1] = Zk;
        S[q2] = Zk2;
    }
    __syncthreads();

    inv_group16(S, tid);   __syncthreads();
    inv_group3<4>(S, tid); __syncthreads();
    inv_group3<7>(S, tid); __syncthreads();

    const float invN = 1.0f / 8192.0f;
    float bv = bias[d];
    float2* orow = (float2*)(g_yT + (size_t)col * SEQ_LEN);
    inv_pass4_fused(S, tid, orow, invN, bv);
}

// ---------------- launch ----------------
extern "C" void kernel_launch(void* const* d_in, const int* in_sizes, int n_in,
                              void* d_out, int out_size) {
    const float* x       = (const float*)d_in[0];
    const float* w_in    = (const float*)d_in[1];
    const float* b_in    = (const float*)d_in[2];
    const float* freq_in = (const float*)d_in[3];
    const float* w_h0    = (const float*)d_in[4];
    const float* b_h0    = (const float*)d_in[5];
    const float* freq_h0 = (const float*)d_in[6];
    const float* w_h1    = (const float*)d_in[7];
    const float* b_h1    = (const float*)d_in[8];
    const float* freq_h1 = (const float*)d_in[9];
    const float* w_out   = (const float*)d_in[10];
    const float* bias    = (const float*)d_in[11];
    float* out = (float*)d_out;

    const int FILTER_SMEM = (2048 + 768 * 17) * 4;   // 60416 B

    cudaFuncSetAttribute(kf_kernel,     cudaFuncAttributeMaxDynamicSharedMemorySize, SMEM_BYTES);
    cudaFuncSetAttribute(conv_kernel,   cudaFuncAttributeMaxDynamicSharedMemorySize, SMEM_BYTES);
    cudaFuncSetAttribute(filter_kernel, cudaFuncAttributeMaxDynamicSharedMemorySize, FILTER_SMEM);

    twiddle_init<<<16, 512>>>();
    filter_kernel<<<SEQ_LEN / 16, 256, FILTER_SMEM>>>(w_in, b_in, freq_in, w_h0, b_h0, freq_h0,
                                                      w_h1, b_h1, freq_h1, w_out);
    dim3 tblk(32, 8);
    dim3 tgrid(SEQ_LEN / 128, HIDDEN / 32, BATCH);
    transpose_in<<<tgrid, tblk>>>(x);
    kf_kernel<<<HIDDEN, 512, SMEM_BYTES>>>();
    conv_kernel<<<BATCH * HIDDEN, 512, SMEM_BYTES>>>(bias);
    transpose_out<<<tgrid, tblk>>>(out);
}